// round 15
// baseline (speedup 1.0000x reference)
#include <cuda_runtime.h>
#include <cuda_fp16.h>
#include <cstdint>
#include <math.h>

#define MUL0 16
#define MUL1 8
#define DIM_F 40
#define NRB 16
#define NRD 64
#define W_NUMEL 576

#define THREADS 256
#define E_TILE 128
#define GRID 296
#define XP 52            // x_s row pitch (floats, 16B-aligned): 40 x | 8 dot | 3 sh | pad

// ---- smem layout (bytes) ----
static constexpr int OFF_B   = 0;          // W2 hi fp16 [576 n][64 k], 128B rows, XOR-swz (73728)
static constexpr int OFF_EH  = 73728;      // emb hi fp16 [128 e][16 k], 32B rows (4096)
static constexpr int OFF_EL  = 77824;      // emb lo (4096)
static constexpr int OFF_W1H = 81920;      // W1^T hi fp16 [64 d][16 k], 32B rows (2048)
static constexpr int OFF_W1L = 83968;      // W1^T lo (2048)
static constexpr int OFF_X   = 86016;      // x_s [128][52] f32 (26624)
static constexpr int OFF_DST = 112640;     // dst_s [128] int (512)
static constexpr int SMEM_TOTAL = 113152;  // fits 2 CTAs/SM (226304 <= 228KB)

__device__ __forceinline__ float silu_scaled(float z) {   // silu(z/4)/8
    float a = z * 0.25f, th;
    asm("tanh.approx.f32 %0, %1;" : "=f"(th) : "f"(a * 0.5f));
    return a * (1.0f + th) * 0.0625f;
}
__device__ __forceinline__ void mma_f16(float* d, const uint32_t* a, const uint32_t* b) {
    asm volatile("mma.sync.aligned.m16n8k16.row.col.f32.f16.f16.f32 "
        "{%0,%1,%2,%3}, {%4,%5,%6,%7}, {%8,%9}, {%0,%1,%2,%3};"
        : "+f"(d[0]), "+f"(d[1]), "+f"(d[2]), "+f"(d[3])
        : "r"(a[0]), "r"(a[1]), "r"(a[2]), "r"(a[3]), "r"(b[0]), "r"(b[1]));
}
#define LDSM_X4(r, addr) \
    asm volatile("ldmatrix.sync.aligned.m8n8.x4.shared.b16 {%0,%1,%2,%3}, [%4];" \
        : "=r"((r)[0]), "=r"((r)[1]), "=r"((r)[2]), "=r"((r)[3]) : "r"(addr))

__device__ __forceinline__ uint32_t smem_u32(const void* p) {
    uint32_t a;
    asm("{ .reg .u64 t; cvta.to.shared.u64 t, %1; cvt.u32.u64 %0, t; }" : "=r"(a) : "l"(p));
    return a;
}

__global__ void zero_kernel(float4* __restrict__ out, int n4) {
    int i = blockIdx.x * blockDim.x + threadIdx.x;
    if (i < n4) out[i] = make_float4(0.f, 0.f, 0.f, 0.f);
}

__global__ __launch_bounds__(THREADS, 2)
void conv_kernel(const float* __restrict__ pos,
                 const float* __restrict__ f_in,
                 const int*   __restrict__ edge_src,
                 const int*   __restrict__ edge_dst,
                 const float* __restrict__ W1,
                 const float* __restrict__ W2,
                 float* __restrict__ f_out,
                 int n_edges)
{
    extern __shared__ char smem[];
    const uint32_t sb = smem_u32(smem);
    const int tid  = threadIdx.x;
    const int warp = tid >> 5;
    const int lane = tid & 31;
    const int g    = lane >> 2;       // mma octet id
    const int c    = lane & 3;        // k-pair / col-pair selector
    const int mi   = warp & 3;        // m-group: rows 32*mi .. 32*mi+31
    const int ni   = warp >> 2;       // n-half: cols 16*ni .. +15 of each chunk
    const int li   = lane & 7;        // ldmatrix row index
    const int sel  = lane >> 3;       // ldmatrix matrix selector

    float* x_s  = reinterpret_cast<float*>(smem + OFF_X);
    int*   dst_s = reinterpret_cast<int*>(smem + OFF_DST);

    // ---- stage W2 hi (fp16, XOR-swz) and W1^T hi/lo once per block ----
    for (int idx = tid; idx < NRD * W_NUMEL; idx += THREADS) {
        int k = idx / W_NUMEL, n = idx - k * W_NUMEL;
        __half hb = __float2half_rn(W2[idx]);
        int kb = k * 2;
        int off = n * 128 + (kb & 15) + 16 * (((kb >> 4) ^ n) & 7);
        *reinterpret_cast<__half*>(smem + OFF_B + off) = hb;
    }
    for (int idx = tid; idx < NRB * NRD; idx += THREADS) {
        int k = idx >> 6;       // W1 row (radial basis index)
        int d = idx & 63;       // W1 col (hidden dim)
        float v = W1[idx];
        __half hb = __float2half_rn(v);
        __half lb = __float2half_rn(v - __half2float(hb));
        *reinterpret_cast<__half*>(smem + OFF_W1H + d * 32 + k * 2) = hb;
        *reinterpret_cast<__half*>(smem + OFF_W1L + d * 32 + k * 2) = lb;
    }
    __syncthreads();

    const int n_tiles = (n_edges + E_TILE - 1) / E_TILE;
    const int le0 = 32 * mi + g;                 // edges owned: le0 + 8j, j = 0..3

    for (int tile = blockIdx.x; tile < n_tiles; tile += gridDim.x) {
        // ============ Phase 1: 2 threads per edge ============
        {
            const int e    = tid >> 1;
            const int role = tid & 1;
            int eg = tile * E_TILE + e;
            int valid = (eg < n_edges);
            float* xs = x_s + e * XP;
            if (role == 0) {
                // gather f_in row via cp.async (10 x 16B)
                int es = valid ? edge_src[eg] : 0;
                const char* gsrc = reinterpret_cast<const char*>(f_in + (size_t)es * DIM_F);
                uint32_t dsts = sb + OFF_X + (uint32_t)(e * XP) * 4u;
                #pragma unroll
                for (int q = 0; q < 10; q++)
                    asm volatile("cp.async.ca.shared.global [%0], [%1], 16;"
                                 :: "r"(dsts + q * 16), "l"(gsrc + q * 16) : "memory");
                asm volatile("cp.async.commit_group;" ::: "memory");
            } else {
                // geometry + radial embedding
                int es = valid ? edge_src[eg] : 0;
                int ed = valid ? edge_dst[eg] : 0;
                float r = 1e9f, s0 = 0.f, s1 = 0.f, s2 = 0.f;
                if (valid) {
                    float ax = pos[es * 3 + 0], ay = pos[es * 3 + 1], az = pos[es * 3 + 2];
                    float bx = pos[ed * 3 + 0], by = pos[ed * 3 + 1], bz = pos[ed * 3 + 2];
                    float dx = bx - ax, dy = by - ay, dz = bz - az;
                    r = sqrtf(dx * dx + dy * dy + dz * dz + 1e-12f);
                    float inv = 1.7320508075688772f / r;   // sqrt(3)/r
                    s0 = dx * inv; s1 = dy * inv; s2 = dz * inv;
                }
                dst_s[e] = ed;
                xs[48] = s0; xs[49] = s1; xs[50] = s2;
                // radial embedding -> fp16 hi/lo emb tiles
                float embv[NRB];
                #pragma unroll
                for (int i = 0; i < NRB; i++) {
                    float v = (5.0f / 17.0f) * (float)(i + 1);
                    float d = (r - v) * 3.4f;
                    float d2 = d * d;
                    float y = 0.0f;
                    if (d2 < 1.0f) y = 4.56544f * __expf(2.0f - __fdividef(2.0f, 1.0f - d2));
                    embv[i] = y;
                }
                #pragma unroll
                for (int i2 = 0; i2 < 8; i2++) {
                    float v0 = embv[2 * i2], v1 = embv[2 * i2 + 1];
                    __half h0 = __float2half_rn(v0), h1 = __float2half_rn(v1);
                    __half l0 = __float2half_rn(v0 - __half2float(h0));
                    __half l1 = __float2half_rn(v1 - __half2float(h1));
                    __half2 ph = __halves2half2(h0, h1);
                    __half2 pl = __halves2half2(l0, l1);
                    *reinterpret_cast<uint32_t*>(smem + OFF_EH + e * 32 + i2 * 4) =
                        *reinterpret_cast<uint32_t*>(&ph);
                    *reinterpret_cast<uint32_t*>(smem + OFF_EL + e * 32 + i2 * 4) =
                        *reinterpret_cast<uint32_t*>(&pl);
                }
            }
            if (role == 0)
                asm volatile("cp.async.wait_group 0;" ::: "memory");
            __syncwarp();
            if (role == 0) {
                // dot products (x now visible to issuing thread; sh via syncwarp)
                float s0 = xs[48], s1 = xs[49], s2 = xs[50];
                #pragma unroll
                for (int u = 0; u < MUL1; u++) {
                    float dv = xs[16 + u * 3 + 0] * s0 + xs[16 + u * 3 + 1] * s1
                             + xs[16 + u * 3 + 2] * s2;
                    xs[40 + u] = dv * 0.57735026918962576f;   // 1/sqrt(3)
                }
            }
        }
        __syncthreads();

        // ============ Phase 2: h-MLP via HMMA -> A fragments directly in registers ============
        uint32_t Ahi[2][4][4];
        {
            uint32_t eh[2][4], el[2][4];
            #pragma unroll
            for (int mf = 0; mf < 2; mf++) {
                int rb = 32 * mi + 16 * mf;
                int o0 = (rb + g) * 32 + 4 * c;
                int o1 = (rb + g + 8) * 32 + 4 * c;
                eh[mf][0] = *reinterpret_cast<const uint32_t*>(smem + OFF_EH + o0);
                eh[mf][1] = *reinterpret_cast<const uint32_t*>(smem + OFF_EH + o1);
                eh[mf][2] = *reinterpret_cast<const uint32_t*>(smem + OFF_EH + o0 + 16);
                eh[mf][3] = *reinterpret_cast<const uint32_t*>(smem + OFF_EH + o1 + 16);
                el[mf][0] = *reinterpret_cast<const uint32_t*>(smem + OFF_EL + o0);
                el[mf][1] = *reinterpret_cast<const uint32_t*>(smem + OFF_EL + o1);
                el[mf][2] = *reinterpret_cast<const uint32_t*>(smem + OFF_EL + o0 + 16);
                el[mf][3] = *reinterpret_cast<const uint32_t*>(smem + OFF_EL + o1 + 16);
            }
            #pragma unroll
            for (int j = 0; j < 4; j++) {         // j = big-GEMM k-chunk
                float hz[2][2][4];
                #pragma unroll
                for (int mf = 0; mf < 2; mf++)
                    #pragma unroll
                    for (int t = 0; t < 2; t++)
                        #pragma unroll
                        for (int q = 0; q < 4; q++) hz[mf][t][q] = 0.f;
                #pragma unroll
                for (int t = 0; t < 2; t++) {     // n-tile nt = 2j + t (d cols)
                    int n = (2 * j + t) * 8 + g;
                    uint32_t bh[2], bl[2];
                    bh[0] = *reinterpret_cast<const uint32_t*>(smem + OFF_W1H + n * 32 + 4 * c);
                    bh[1] = *reinterpret_cast<const uint32_t*>(smem + OFF_W1H + n * 32 + 16 + 4 * c);
                    bl[0] = *reinterpret_cast<const uint32_t*>(smem + OFF_W1L + n * 32 + 4 * c);
                    bl[1] = *reinterpret_cast<const uint32_t*>(smem + OFF_W1L + n * 32 + 16 + 4 * c);
                    #pragma unroll
                    for (int mf = 0; mf < 2; mf++) {
                        mma_f16(hz[mf][t], eh[mf], bh);
                        mma_f16(hz[mf][t], el[mf], bh);
                        mma_f16(hz[mf][t], eh[mf], bl);
                    }
                }
                #pragma unroll
                for (int mf = 0; mf < 2; mf++)
                    #pragma unroll
                    for (int t = 0; t < 2; t++) {
                        float s0 = silu_scaled(hz[mf][t][0]);
                        float s1 = silu_scaled(hz[mf][t][1]);
                        float s2 = silu_scaled(hz[mf][t][2]);
                        float s3 = silu_scaled(hz[mf][t][3]);
                        __half2 p01 = __floats2half2_rn(s0, s1);
                        __half2 p23 = __floats2half2_rn(s2, s3);
                        Ahi[mf][j][2 * t + 0] = *reinterpret_cast<uint32_t*>(&p01);
                        Ahi[mf][j][2 * t + 1] = *reinterpret_cast<uint32_t*>(&p23);
                    }
            }
        }

        // per-edge TP partials: 4 edges (le0, +8, +16, +24)
        float po0p[4][4], cfp[4][2], tpp[4][2][3];
        #pragma unroll
        for (int j = 0; j < 4; j++) {
            #pragma unroll
            for (int s = 0; s < 4; s++) po0p[j][s] = 0.f;
            cfp[j][0] = 0.f; cfp[j][1] = 0.f;
            #pragma unroll
            for (int b = 0; b < 2; b++)
                #pragma unroll
                for (int k = 0; k < 3; k++) tpp[j][b][k] = 0.f;
        }

        // ============ Phase 4: 18 GEMM chunks, B via ldmatrix.x4, consumed in-register ============
        for (int cc = 0; cc < 18; cc++) {
            float acc[2][2][4];
            #pragma unroll
            for (int mf = 0; mf < 2; mf++)
                #pragma unroll
                for (int nt = 0; nt < 2; nt++)
                    #pragma unroll
                    for (int q = 0; q < 4; q++) acc[mf][nt][q] = 0.f;

            #pragma unroll
            for (int ks = 0; ks < 4; ks++) {
                uint32_t bh[4];
                {
                    int nrow = cc * 32 + ni * 16 + (sel >> 1) * 8 + li;
                    int ch   = 2 * ks + (sel & 1);
                    uint32_t addr = sb + OFF_B + nrow * 128 + 16 * ((ch ^ nrow) & 7);
                    LDSM_X4(bh, addr);
                }
                #pragma unroll
                for (int mf = 0; mf < 2; mf++)
                    #pragma unroll
                    for (int nt = 0; nt < 2; nt++)
                        mma_f16(acc[mf][nt], Ahi[mf][ks], &bh[2 * nt]);
            }

            // ---- consume: row = edge, col = 32cc + 16ni + 8nt + 2c + (q&1) ----
            if (cc < 8) {                          // w00: u = 2cc+ni (uniform)
                int u = 2 * cc + ni;
                float xv[4];
                #pragma unroll
                for (int j = 0; j < 4; j++) xv[j] = x_s[(le0 + 8 * j) * XP + u];
                #pragma unroll
                for (int mf = 0; mf < 2; mf++)
                    #pragma unroll
                    for (int nt = 0; nt < 2; nt++)
                        #pragma unroll
                        for (int q = 0; q < 4; q++) {
                            int j = 2 * mf + (q >> 1);
                            po0p[j][2 * nt + (q & 1)] =
                                fmaf(acc[mf][nt][q], xv[j], po0p[j][2 * nt + (q & 1)]);
                        }
            } else if (cc < 12) {                  // w01: u = 4(cc-8)+2ni+nt
                int ub = 4 * (cc - 8) + 2 * ni;
                float xv[4][2];
                #pragma unroll
                for (int j = 0; j < 4; j++) {
                    xv[j][0] = x_s[(le0 + 8 * j) * XP + ub];
                    xv[j][1] = x_s[(le0 + 8 * j) * XP + ub + 1];
                }
                #pragma unroll
                for (int mf = 0; mf < 2; mf++)
                    #pragma unroll
                    for (int nt = 0; nt < 2; nt++)
                        #pragma unroll
                        for (int q = 0; q < 4; q++) {
                            int j = 2 * mf + (q >> 1);
                            cfp[j][q & 1] = fmaf(acc[mf][nt][q], xv[j][nt], cfp[j][q & 1]);
                        }
            } else if (cc < 14) {                  // w10: u = 4(cc-12)+2ni+nt
                int ub = 4 * (cc - 12) + 2 * ni;
                float xv[4][2][3];
                #pragma unroll
                for (int j = 0; j < 4; j++)
                    #pragma unroll
                    for (int nt = 0; nt < 2; nt++)
                        #pragma unroll
                        for (int k = 0; k < 3; k++)
                            xv[j][nt][k] = x_s[(le0 + 8 * j) * XP + 16 + 3 * (ub + nt) + k];
                #pragma unroll
                for (int mf = 0; mf < 2; mf++)
                    #pragma unroll
                    for (int nt = 0; nt < 2; nt++)
                        #pragma unroll
                        for (int q = 0; q < 4; q++) {
                            int j = 2 * mf + (q >> 1);
                            #pragma unroll
                            for (int k = 0; k < 3; k++)
                                tpp[j][q & 1][k] =
                                    fmaf(acc[mf][nt][q], xv[j][nt][k], tpp[j][q & 1][k]);
                        }
            } else {                               // w11: u = 2(cc-14)+ni
                int u = 2 * (cc - 14) + ni;
                float dv[4];
                #pragma unroll
                for (int j = 0; j < 4; j++) dv[j] = x_s[(le0 + 8 * j) * XP + 40 + u];
                #pragma unroll
                for (int mf = 0; mf < 2; mf++)
                    #pragma unroll
                    for (int nt = 0; nt < 2; nt++)
                        #pragma unroll
                        for (int q = 0; q < 4; q++) {
                            int j = 2 * mf + (q >> 1);
                            po0p[j][2 * nt + (q & 1)] =
                                fmaf(acc[mf][nt][q], dv[j], po0p[j][2 * nt + (q & 1)]);
                        }
            }
        }

        // ============ Phase 5: direct scatter (both ni warps; partials linear) ============
        {
            const float SC = 0.05103103630798288f;   // 1/(sqrt(24)*4)
            #pragma unroll
            for (int j = 0; j < 4; j++) {
                int le = le0 + 8 * j;
                if (tile * E_TILE + le < n_edges) {
                    const float* xs = x_s + le * XP;
                    float s0 = xs[48], s1 = xs[49], s2 = xs[50];
                    int dst = dst_s[le];
                    float* base = f_out + (size_t)dst * DIM_F;
                    asm volatile("red.global.add.v2.f32 [%0], {%1, %2};"
                                 :: "l"(base + 2 * c),
                                    "f"(po0p[j][0] * SC), "f"(po0p[j][1] * SC) : "memory");
                    asm volatile("red.global.add.v2.f32 [%0], {%1, %2};"
                                 :: "l"(base + 8 + 2 * c),
                                    "f"(po0p[j][2] * SC), "f"(po0p[j][3] * SC) : "memory");
                    float o0 = (cfp[j][0] * s0 + tpp[j][0][0]) * SC;
                    float o1 = (cfp[j][0] * s1 + tpp[j][0][1]) * SC;
                    float o2 = (cfp[j][0] * s2 + tpp[j][0][2]) * SC;
                    float o3 = (cfp[j][1] * s0 + tpp[j][1][0]) * SC;
                    float o4 = (cfp[j][1] * s1 + tpp[j][1][1]) * SC;
                    float o5 = (cfp[j][1] * s2 + tpp[j][1][2]) * SC;
                    float* b1 = base + 16 + 6 * c;
                    asm volatile("red.global.add.v2.f32 [%0], {%1, %2};"
                                 :: "l"(b1), "f"(o0), "f"(o1) : "memory");
                    asm volatile("red.global.add.v2.f32 [%0], {%1, %2};"
                                 :: "l"(b1 + 2), "f"(o2), "f"(o3) : "memory");
                    asm volatile("red.global.add.v2.f32 [%0], {%1, %2};"
                                 :: "l"(b1 + 4), "f"(o4), "f"(o5) : "memory");
                }
            }
        }
        __syncthreads();    // protect x_s / emb before next tile overwrites
    }
}

extern "C" void kernel_launch(void* const* d_in, const int* in_sizes, int n_in,
                              void* d_out, int out_size) {
    const float* pos  = (const float*)d_in[0];
    const float* f_in = (const float*)d_in[1];
    const int*   esrc = (const int*)d_in[2];
    const int*   edst = (const int*)d_in[3];
    const float* W1   = (const float*)d_in[4];
    const float* W2   = (const float*)d_in[5];
    float* out = (float*)d_out;
    int n_edges = in_sizes[2];

    cudaFuncSetAttribute(conv_kernel, cudaFuncAttributeMaxDynamicSharedMemorySize, SMEM_TOTAL);

    int n4 = out_size / 4;
    zero_kernel<<<(n4 + 255) / 256, 256>>>((float4*)out, n4);
    conv_kernel<<<GRID, THREADS, SMEM_TOTAL>>>(pos, f_in, esrc, edst, W1, W2, out, n_edges);
}

// round 16
// speedup vs baseline: 1.1071x; 1.1071x over previous
#include <cuda_runtime.h>
#include <cuda_fp16.h>
#include <cstdint>
#include <math.h>

#define MUL0 16
#define MUL1 8
#define DIM_F 40
#define NRB 16
#define NRD 64
#define W_NUMEL 576

#define THREADS 256
#define E_TILE 128
#define GRID 296
#define XP 53            // x_s row pitch (floats): 40 x | 8 dot | 3 sh | rr | dst

// ---- smem layout (bytes) ----
static constexpr int OFF_B   = 0;          // W2 hi fp16 [576 n][64 k], 128B rows, XOR-swz (73728)
static constexpr int OFF_EH  = 73728;      // emb hi fp16 [128 e][16 k], 32B rows (4096)
static constexpr int OFF_W1H = 77824;      // W1^T hi fp16 [64 d][16 k], 32B rows (2048)
static constexpr int OFF_W1L = 79872;      // W1^T lo (2048)
static constexpr int OFF_X   = 81920;      // x_s [128][53] f32 (27136)
static constexpr int SMEM_TOTAL = 109056;  // fits 2 CTAs/SM

__device__ __forceinline__ float silu_scaled(float z) {   // silu(z/4)/8
    float a = z * 0.25f, th;
    asm("tanh.approx.f32 %0, %1;" : "=f"(th) : "f"(a * 0.5f));
    return a * (1.0f + th) * 0.0625f;
}
__device__ __forceinline__ void mma_f16(float* d, const uint32_t* a, const uint32_t* b) {
    asm volatile("mma.sync.aligned.m16n8k16.row.col.f32.f16.f16.f32 "
        "{%0,%1,%2,%3}, {%4,%5,%6,%7}, {%8,%9}, {%0,%1,%2,%3};"
        : "+f"(d[0]), "+f"(d[1]), "+f"(d[2]), "+f"(d[3])
        : "r"(a[0]), "r"(a[1]), "r"(a[2]), "r"(a[3]), "r"(b[0]), "r"(b[1]));
}
#define LDSM_X4(r, addr) \
    asm volatile("ldmatrix.sync.aligned.m8n8.x4.shared.b16 {%0,%1,%2,%3}, [%4];" \
        : "=r"((r)[0]), "=r"((r)[1]), "=r"((r)[2]), "=r"((r)[3]) : "r"(addr))

__device__ __forceinline__ uint32_t smem_u32(const void* p) {
    uint32_t a;
    asm("{ .reg .u64 t; cvta.to.shared.u64 t, %1; cvt.u32.u64 %0, t; }" : "=r"(a) : "l"(p));
    return a;
}

// GEMM for one 32-col chunk: B via ldmatrix.x4, acc[2][2][4]
#define GEMM_CHUNK(cc_) do { \
    _Pragma("unroll") \
    for (int mf_ = 0; mf_ < 2; mf_++) \
        _Pragma("unroll") \
        for (int nt_ = 0; nt_ < 2; nt_++) \
            _Pragma("unroll") \
            for (int q_ = 0; q_ < 4; q_++) acc[mf_][nt_][q_] = 0.f; \
    _Pragma("unroll") \
    for (int ks_ = 0; ks_ < 4; ks_++) { \
        uint32_t bh_[4]; \
        { \
            int nrow_ = (cc_) * 32 + ni * 16 + (sel >> 1) * 8 + li; \
            int ch_   = 2 * ks_ + (sel & 1); \
            uint32_t addr_ = sb + OFF_B + nrow_ * 128 + 16 * ((ch_ ^ nrow_) & 7); \
            LDSM_X4(bh_, addr_); \
        } \
        _Pragma("unroll") \
        for (int mf_ = 0; mf_ < 2; mf_++) \
            _Pragma("unroll") \
            for (int nt_ = 0; nt_ < 2; nt_++) \
                mma_f16(acc[mf_][nt_], Ahi[mf_][ks_], &bh_[2 * nt_]); \
    } } while (0)

__global__ void zero_kernel(float4* __restrict__ out, int n4) {
    int i = blockIdx.x * blockDim.x + threadIdx.x;
    if (i < n4) out[i] = make_float4(0.f, 0.f, 0.f, 0.f);
}

__global__ __launch_bounds__(THREADS, 2)
void conv_kernel(const float* __restrict__ pos,
                 const float* __restrict__ f_in,
                 const int*   __restrict__ edge_src,
                 const int*   __restrict__ edge_dst,
                 const float* __restrict__ W1,
                 const float* __restrict__ W2,
                 float* __restrict__ f_out,
                 int n_edges)
{
    extern __shared__ char smem[];
    const uint32_t sb = smem_u32(smem);
    const int tid  = threadIdx.x;
    const int warp = tid >> 5;
    const int lane = tid & 31;
    const int g    = lane >> 2;       // mma octet id
    const int c    = lane & 3;        // k-pair / col-pair selector
    const int mi   = warp & 3;        // m-group: rows 32*mi .. 32*mi+31
    const int ni   = warp >> 2;       // n-half: cols 16*ni .. +15 of each chunk
    const int li   = lane & 7;        // ldmatrix row index
    const int sel  = lane >> 3;       // ldmatrix matrix selector

    float* x_s = reinterpret_cast<float*>(smem + OFF_X);

    // ---- stage W2 hi (fp16, XOR-swz) and W1^T hi/lo once per block ----
    for (int idx = tid; idx < NRD * W_NUMEL; idx += THREADS) {
        int k = idx / W_NUMEL, n = idx - k * W_NUMEL;
        __half hb = __float2half_rn(W2[idx]);
        int kb = k * 2;
        int off = n * 128 + (kb & 15) + 16 * (((kb >> 4) ^ n) & 7);
        *reinterpret_cast<__half*>(smem + OFF_B + off) = hb;
    }
    for (int idx = tid; idx < NRB * NRD; idx += THREADS) {
        int k = idx >> 6;       // W1 row (radial basis index)
        int d = idx & 63;       // W1 col (hidden dim)
        float v = W1[idx];
        __half hb = __float2half_rn(v);
        __half lb = __float2half_rn(v - __half2float(hb));
        *reinterpret_cast<__half*>(smem + OFF_W1H + d * 32 + k * 2) = hb;
        *reinterpret_cast<__half*>(smem + OFF_W1L + d * 32 + k * 2) = lb;
    }
    __syncthreads();

    const int n_tiles = (n_edges + E_TILE - 1) / E_TILE;
    const int le0 = 32 * mi + g;                 // edges owned: le0 + 8j, j = 0..3

    for (int tile = blockIdx.x; tile < n_tiles; tile += gridDim.x) {
        // ============ Phase 1: geometry + x gather + radial emb (thread = edge) ============
        if (tid < E_TILE) {
            int e = tile * E_TILE + tid;
            float* xs = x_s + tid * XP;
            float r = 1e9f;
            float s0 = 0.f, s1 = 0.f, s2 = 0.f;
            int es = 0, ed = 0;
            if (e < n_edges) {
                es = edge_src[e]; ed = edge_dst[e];
                float ax = pos[es * 3 + 0], ay = pos[es * 3 + 1], az = pos[es * 3 + 2];
                float bx = pos[ed * 3 + 0], by = pos[ed * 3 + 1], bz = pos[ed * 3 + 2];
                float dx = bx - ax, dy = by - ay, dz = bz - az;
                r = sqrtf(dx * dx + dy * dy + dz * dz + 1e-12f);
                float inv = 1.7320508075688772f / r;       // sqrt(3)/r
                s0 = dx * inv; s1 = dy * inv; s2 = dz * inv;
            }
            const float4* frow = reinterpret_cast<const float4*>(f_in + (size_t)es * DIM_F);
            float xr[DIM_F];
            #pragma unroll
            for (int q = 0; q < 10; q++) {
                float4 v = frow[q];
                xr[q * 4 + 0] = v.x; xr[q * 4 + 1] = v.y;
                xr[q * 4 + 2] = v.z; xr[q * 4 + 3] = v.w;
            }
            #pragma unroll
            for (int q = 0; q < DIM_F; q++) xs[q] = xr[q];
            #pragma unroll
            for (int u = 0; u < MUL1; u++) {
                float dv = xr[16 + u * 3 + 0] * s0 + xr[16 + u * 3 + 1] * s1
                         + xr[16 + u * 3 + 2] * s2;
                xs[40 + u] = dv * 0.57735026918962576f;    // 1/sqrt(3)
            }
            xs[48] = s0; xs[49] = s1; xs[50] = s2;
            xs[51] = r;
            xs[52] = __int_as_float(ed);
            // radial embedding -> fp16 hi emb tile
            float embv[NRB];
            #pragma unroll
            for (int i = 0; i < NRB; i++) {
                float v = (5.0f / 17.0f) * (float)(i + 1);
                float d = (r - v) * 3.4f;
                float d2 = d * d;
                float y = 0.0f;
                if (d2 < 1.0f) y = 4.56544f * __expf(2.0f - __fdividef(2.0f, 1.0f - d2));
                embv[i] = y;
            }
            #pragma unroll
            for (int i2 = 0; i2 < 8; i2++) {
                __half2 ph = __floats2half2_rn(embv[2 * i2], embv[2 * i2 + 1]);
                *reinterpret_cast<uint32_t*>(smem + OFF_EH + tid * 32 + i2 * 4) =
                    *reinterpret_cast<uint32_t*>(&ph);
            }
        }
        __syncthreads();

        // ============ Phase 2: h-MLP via HMMA -> A fragments directly in registers ============
        uint32_t Ahi[2][4][4];
        {
            uint32_t eh[2][4];
            #pragma unroll
            for (int mf = 0; mf < 2; mf++) {
                int rb = 32 * mi + 16 * mf;
                int o0 = (rb + g) * 32 + 4 * c;
                int o1 = (rb + g + 8) * 32 + 4 * c;
                eh[mf][0] = *reinterpret_cast<const uint32_t*>(smem + OFF_EH + o0);
                eh[mf][1] = *reinterpret_cast<const uint32_t*>(smem + OFF_EH + o1);
                eh[mf][2] = *reinterpret_cast<const uint32_t*>(smem + OFF_EH + o0 + 16);
                eh[mf][3] = *reinterpret_cast<const uint32_t*>(smem + OFF_EH + o1 + 16);
            }
            #pragma unroll
            for (int j = 0; j < 4; j++) {         // j = big-GEMM k-chunk
                float hz[2][2][4];
                #pragma unroll
                for (int mf = 0; mf < 2; mf++)
                    #pragma unroll
                    for (int t = 0; t < 2; t++)
                        #pragma unroll
                        for (int q = 0; q < 4; q++) hz[mf][t][q] = 0.f;
                #pragma unroll
                for (int t = 0; t < 2; t++) {     // n-tile nt = 2j + t (d cols)
                    int n = (2 * j + t) * 8 + g;
                    uint32_t bh[2], bl[2];
                    bh[0] = *reinterpret_cast<const uint32_t*>(smem + OFF_W1H + n * 32 + 4 * c);
                    bh[1] = *reinterpret_cast<const uint32_t*>(smem + OFF_W1H + n * 32 + 16 + 4 * c);
                    bl[0] = *reinterpret_cast<const uint32_t*>(smem + OFF_W1L + n * 32 + 4 * c);
                    bl[1] = *reinterpret_cast<const uint32_t*>(smem + OFF_W1L + n * 32 + 16 + 4 * c);
                    #pragma unroll
                    for (int mf = 0; mf < 2; mf++) {
                        mma_f16(hz[mf][t], eh[mf], bh);
                        mma_f16(hz[mf][t], eh[mf], bl);
                    }
                }
                #pragma unroll
                for (int mf = 0; mf < 2; mf++)
                    #pragma unroll
                    for (int t = 0; t < 2; t++) {
                        float s0 = silu_scaled(hz[mf][t][0]);
                        float s1 = silu_scaled(hz[mf][t][1]);
                        float s2 = silu_scaled(hz[mf][t][2]);
                        float s3 = silu_scaled(hz[mf][t][3]);
                        __half2 p01 = __floats2half2_rn(s0, s1);
                        __half2 p23 = __floats2half2_rn(s2, s3);
                        Ahi[mf][j][2 * t + 0] = *reinterpret_cast<uint32_t*>(&p01);
                        Ahi[mf][j][2 * t + 1] = *reinterpret_cast<uint32_t*>(&p23);
                    }
            }
        }

        // per-edge TP partials: 4 edges (le0, +8, +16, +24)
        float po0p[4][4], cfp[4][2], tpp[4][2][3];
        #pragma unroll
        for (int j = 0; j < 4; j++) {
            #pragma unroll
            for (int s = 0; s < 4; s++) po0p[j][s] = 0.f;
            cfp[j][0] = 0.f; cfp[j][1] = 0.f;
            #pragma unroll
            for (int b = 0; b < 2; b++)
                #pragma unroll
                for (int k = 0; k < 3; k++) tpp[j][b][k] = 0.f;
        }

        // ============ Phase 4: type-specialized GEMM+consume loops ============
        float acc[2][2][4];

        // -- w00: cc in [0,8), u = 2cc + ni --
        for (int cc = 0; cc < 8; cc++) {
            GEMM_CHUNK(cc);
            int u = 2 * cc + ni;
            float xv[4];
            #pragma unroll
            for (int j = 0; j < 4; j++) xv[j] = x_s[(le0 + 8 * j) * XP + u];
            #pragma unroll
            for (int mf = 0; mf < 2; mf++)
                #pragma unroll
                for (int nt = 0; nt < 2; nt++)
                    #pragma unroll
                    for (int q = 0; q < 4; q++) {
                        int j = 2 * mf + (q >> 1);
                        po0p[j][2 * nt + (q & 1)] =
                            fmaf(acc[mf][nt][q], xv[j], po0p[j][2 * nt + (q & 1)]);
                    }
        }
        // -- w01: cc in [8,12), u = 4(cc-8) + 2ni + nt --
        for (int cc = 8; cc < 12; cc++) {
            GEMM_CHUNK(cc);
            int ub = 4 * (cc - 8) + 2 * ni;
            float xv[4][2];
            #pragma unroll
            for (int j = 0; j < 4; j++) {
                xv[j][0] = x_s[(le0 + 8 * j) * XP + ub];
                xv[j][1] = x_s[(le0 + 8 * j) * XP + ub + 1];
            }
            #pragma unroll
            for (int mf = 0; mf < 2; mf++)
                #pragma unroll
                for (int nt = 0; nt < 2; nt++)
                    #pragma unroll
                    for (int q = 0; q < 4; q++) {
                        int j = 2 * mf + (q >> 1);
                        cfp[j][q & 1] = fmaf(acc[mf][nt][q], xv[j][nt], cfp[j][q & 1]);
                    }
        }
        // -- w10: cc in [12,14), u = 4(cc-12) + 2ni + nt --
        for (int cc = 12; cc < 14; cc++) {
            GEMM_CHUNK(cc);
            int ub = 4 * (cc - 12) + 2 * ni;
            float xv[4][2][3];
            #pragma unroll
            for (int j = 0; j < 4; j++)
                #pragma unroll
                for (int nt = 0; nt < 2; nt++)
                    #pragma unroll
                    for (int k = 0; k < 3; k++)
                        xv[j][nt][k] = x_s[(le0 + 8 * j) * XP + 16 + 3 * (ub + nt) + k];
            #pragma unroll
            for (int mf = 0; mf < 2; mf++)
                #pragma unroll
                for (int nt = 0; nt < 2; nt++)
                    #pragma unroll
                    for (int q = 0; q < 4; q++) {
                        int j = 2 * mf + (q >> 1);
                        #pragma unroll
                        for (int k = 0; k < 3; k++)
                            tpp[j][q & 1][k] =
                                fmaf(acc[mf][nt][q], xv[j][nt][k], tpp[j][q & 1][k]);
                    }
        }
        // -- w11: cc in [14,18), u = 2(cc-14) + ni --
        for (int cc = 14; cc < 18; cc++) {
            GEMM_CHUNK(cc);
            int u = 2 * (cc - 14) + ni;
            float dv[4];
            #pragma unroll
            for (int j = 0; j < 4; j++) dv[j] = x_s[(le0 + 8 * j) * XP + 40 + u];
            #pragma unroll
            for (int mf = 0; mf < 2; mf++)
                #pragma unroll
                for (int nt = 0; nt < 2; nt++)
                    #pragma unroll
                    for (int q = 0; q < 4; q++) {
                        int j = 2 * mf + (q >> 1);
                        po0p[j][2 * nt + (q & 1)] =
                            fmaf(acc[mf][nt][q], dv[j], po0p[j][2 * nt + (q & 1)]);
                    }
        }

        // ============ Phase 5: direct scatter (both ni warps; partials linear) ============
        {
            const float SC = 0.05103103630798288f;   // 1/(sqrt(24)*4)
            #pragma unroll
            for (int j = 0; j < 4; j++) {
                int le = le0 + 8 * j;
                if (tile * E_TILE + le < n_edges) {
                    const float* xs = x_s + le * XP;
                    float s0 = xs[48], s1 = xs[49], s2 = xs[50];
                    int dst = __float_as_int(xs[52]);
                    float* base = f_out + (size_t)dst * DIM_F;
                    asm volatile("red.global.add.v2.f32 [%0], {%1, %2};"
                                 :: "l"(base + 2 * c),
                                    "f"(po0p[j][0] * SC), "f"(po0p[j][1] * SC) : "memory");
                    asm volatile("red.global.add.v2.f32 [%0], {%1, %2};"
                                 :: "l"(base + 8 + 2 * c),
                                    "f"(po0p[j][2] * SC), "f"(po0p[j][3] * SC) : "memory");
                    float o0 = (cfp[j][0] * s0 + tpp[j][0][0]) * SC;
                    float o1 = (cfp[j][0] * s1 + tpp[j][0][1]) * SC;
                    float o2 = (cfp[j][0] * s2 + tpp[j][0][2]) * SC;
                    float o3 = (cfp[j][1] * s0 + tpp[j][1][0]) * SC;
                    float o4 = (cfp[j][1] * s1 + tpp[j][1][1]) * SC;
                    float o5 = (cfp[j][1] * s2 + tpp[j][1][2]) * SC;
                    float* b1 = base + 16 + 6 * c;
                    asm volatile("red.global.add.v2.f32 [%0], {%1, %2};"
                                 :: "l"(b1), "f"(o0), "f"(o1) : "memory");
                    asm volatile("red.global.add.v2.f32 [%0], {%1, %2};"
                                 :: "l"(b1 + 2), "f"(o2), "f"(o3) : "memory");
                    asm volatile("red.global.add.v2.f32 [%0], {%1, %2};"
                                 :: "l"(b1 + 4), "f"(o4), "f"(o5) : "memory");
                }
            }
        }
        __syncthreads();    // protect x_s / emb before next tile overwrites
    }
}

extern "C" void kernel_launch(void* const* d_in, const int* in_sizes, int n_in,
                              void* d_out, int out_size) {
    const float* pos  = (const float*)d_in[0];
    const float* f_in = (const float*)d_in[1];
    const int*   esrc = (const int*)d_in[2];
    const int*   edst = (const int*)d_in[3];
    const float* W1   = (const float*)d_in[4];
    const float* W2   = (const float*)d_in[5];
    float* out = (float*)d_out;
    int n_edges = in_sizes[2];

    cudaFuncSetAttribute(conv_kernel, cudaFuncAttributeMaxDynamicSharedMemorySize, SMEM_TOTAL);

    int n4 = out_size / 4;
    zero_kernel<<<(n4 + 255) / 256, 256>>>((float4*)out, n4);
    conv_kernel<<<GRID, THREADS, SMEM_TOTAL>>>(pos, f_in, esrc, edst, W1, W2, out, n_edges);
}

// round 17
// speedup vs baseline: 1.1684x; 1.0554x over previous
#include <cuda_runtime.h>
#include <cuda_fp16.h>
#include <cstdint>
#include <math.h>

#define MUL0 16
#define MUL1 8
#define DIM_F 40
#define NRB 16
#define NRD 64
#define W_NUMEL 576

#define THREADS 256
#define E_TILE 128
#define GRID 296
#define XP 53            // x_s row pitch (floats): 40 x | 8 dot | 3 sh | rr | dst

// ---- smem layout (bytes) ----
static constexpr int OFF_B   = 0;          // W2 hi fp16 [576 n][64 k], 128B rows, XOR-swz (73728)
static constexpr int OFF_EH  = 73728;      // emb hi fp16 [128 e][16 k], 32B rows (4096)
static constexpr int OFF_W1H = 77824;      // W1^T hi fp16 [64 d][16 k], 32B rows (2048)
static constexpr int OFF_W1L = 79872;      // W1^T lo (2048)
static constexpr int OFF_X   = 81920;      // x_s [128][53] f32 (27136)
static constexpr int SMEM_TOTAL = 109056;  // fits 2 CTAs/SM

__device__ __forceinline__ float silu_scaled(float z) {   // silu(z/4)/8
    float a = z * 0.25f, th;
    asm("tanh.approx.f32 %0, %1;" : "=f"(th) : "f"(a * 0.5f));
    return a * (1.0f + th) * 0.0625f;
}
__device__ __forceinline__ void mma_f16(float* d, const uint32_t* a, const uint32_t* b) {
    asm volatile("mma.sync.aligned.m16n8k16.row.col.f32.f16.f16.f32 "
        "{%0,%1,%2,%3}, {%4,%5,%6,%7}, {%8,%9}, {%0,%1,%2,%3};"
        : "+f"(d[0]), "+f"(d[1]), "+f"(d[2]), "+f"(d[3])
        : "r"(a[0]), "r"(a[1]), "r"(a[2]), "r"(a[3]), "r"(b[0]), "r"(b[1]));
}
#define LDSM_X4(r, addr) \
    asm volatile("ldmatrix.sync.aligned.m8n8.x4.shared.b16 {%0,%1,%2,%3}, [%4];" \
        : "=r"((r)[0]), "=r"((r)[1]), "=r"((r)[2]), "=r"((r)[3]) : "r"(addr))

__device__ __forceinline__ uint32_t smem_u32(const void* p) {
    uint32_t a;
    asm("{ .reg .u64 t; cvta.to.shared.u64 t, %1; cvt.u32.u64 %0, t; }" : "=r"(a) : "l"(p));
    return a;
}

// GEMM for one 32-col chunk: B via ldmatrix.x4, acc[2][2][4]
#define GEMM_CHUNK(cc_) do { \
    _Pragma("unroll") \
    for (int mf_ = 0; mf_ < 2; mf_++) \
        _Pragma("unroll") \
        for (int nt_ = 0; nt_ < 2; nt_++) \
            _Pragma("unroll") \
            for (int q_ = 0; q_ < 4; q_++) acc[mf_][nt_][q_] = 0.f; \
    _Pragma("unroll") \
    for (int ks_ = 0; ks_ < 4; ks_++) { \
        uint32_t bh_[4]; \
        { \
            int nrow_ = (cc_) * 32 + ni * 16 + (sel >> 1) * 8 + li; \
            int ch_   = 2 * ks_ + (sel & 1); \
            uint32_t addr_ = sb + OFF_B + nrow_ * 128 + 16 * ((ch_ ^ nrow_) & 7); \
            LDSM_X4(bh_, addr_); \
        } \
        _Pragma("unroll") \
        for (int mf_ = 0; mf_ < 2; mf_++) \
            _Pragma("unroll") \
            for (int nt_ = 0; nt_ < 2; nt_++) \
                mma_f16(acc[mf_][nt_], Ahi[mf_][ks_], &bh_[2 * nt_]); \
    } } while (0)

__global__ void zero_kernel(float4* __restrict__ out, int n4) {
    int i = blockIdx.x * blockDim.x + threadIdx.x;
    if (i < n4) out[i] = make_float4(0.f, 0.f, 0.f, 0.f);
}

__global__ __launch_bounds__(THREADS, 2)
void conv_kernel(const float* __restrict__ pos,
                 const float* __restrict__ f_in,
                 const int*   __restrict__ edge_src,
                 const int*   __restrict__ edge_dst,
                 const float* __restrict__ W1,
                 const float* __restrict__ W2,
                 float* __restrict__ f_out,
                 int n_edges)
{
    extern __shared__ char smem[];
    const uint32_t sb = smem_u32(smem);
    const int tid  = threadIdx.x;
    const int warp = tid >> 5;
    const int lane = tid & 31;
    const int g    = lane >> 2;       // mma octet id
    const int c    = lane & 3;        // k-pair / col-pair selector
    const int mi   = warp & 3;        // m-group: rows 32*mi .. 32*mi+31
    const int ni   = warp >> 2;       // n-half: cols 16*ni .. +15 of each chunk
    const int li   = lane & 7;        // ldmatrix row index
    const int sel  = lane >> 3;       // ldmatrix matrix selector

    float* x_s = reinterpret_cast<float*>(smem + OFF_X);

    // ---- stage W2 hi (fp16, XOR-swz) and W1^T hi/lo once per block ----
    for (int idx = tid; idx < NRD * W_NUMEL; idx += THREADS) {
        int k = idx / W_NUMEL, n = idx - k * W_NUMEL;
        __half hb = __float2half_rn(W2[idx]);
        int kb = k * 2;
        int off = n * 128 + (kb & 15) + 16 * (((kb >> 4) ^ n) & 7);
        *reinterpret_cast<__half*>(smem + OFF_B + off) = hb;
    }
    for (int idx = tid; idx < NRB * NRD; idx += THREADS) {
        int k = idx >> 6;       // W1 row (radial basis index)
        int d = idx & 63;       // W1 col (hidden dim)
        float v = W1[idx];
        __half hb = __float2half_rn(v);
        __half lb = __float2half_rn(v - __half2float(hb));
        *reinterpret_cast<__half*>(smem + OFF_W1H + d * 32 + k * 2) = hb;
        *reinterpret_cast<__half*>(smem + OFF_W1L + d * 32 + k * 2) = lb;
    }
    __syncthreads();

    const int n_tiles = (n_edges + E_TILE - 1) / E_TILE;
    const int le0 = 32 * mi + g;                 // edges owned: le0 + 8j, j = 0..3

    for (int tile = blockIdx.x; tile < n_tiles; tile += gridDim.x) {
        // ============ Phase 1: geometry + x gather + radial emb (thread = edge) ============
        if (tid < E_TILE) {
            int e = tile * E_TILE + tid;
            float* xs = x_s + tid * XP;
            float r = 1e9f;
            float s0 = 0.f, s1 = 0.f, s2 = 0.f;
            int es = 0, ed = 0;
            if (e < n_edges) {
                es = edge_src[e]; ed = edge_dst[e];
                float ax = pos[es * 3 + 0], ay = pos[es * 3 + 1], az = pos[es * 3 + 2];
                float bx = pos[ed * 3 + 0], by = pos[ed * 3 + 1], bz = pos[ed * 3 + 2];
                float dx = bx - ax, dy = by - ay, dz = bz - az;
                r = sqrtf(dx * dx + dy * dy + dz * dz + 1e-12f);
                float inv = 1.7320508075688772f / r;       // sqrt(3)/r
                s0 = dx * inv; s1 = dy * inv; s2 = dz * inv;
            }
            const float4* frow = reinterpret_cast<const float4*>(f_in + (size_t)es * DIM_F);
            float xr[DIM_F];
            #pragma unroll
            for (int q = 0; q < 10; q++) {
                float4 v = frow[q];
                xr[q * 4 + 0] = v.x; xr[q * 4 + 1] = v.y;
                xr[q * 4 + 2] = v.z; xr[q * 4 + 3] = v.w;
            }
            #pragma unroll
            for (int q = 0; q < DIM_F; q++) xs[q] = xr[q];
            #pragma unroll
            for (int u = 0; u < MUL1; u++) {
                float dv = xr[16 + u * 3 + 0] * s0 + xr[16 + u * 3 + 1] * s1
                         + xr[16 + u * 3 + 2] * s2;
                xs[40 + u] = dv * 0.57735026918962576f;    // 1/sqrt(3)
            }
            xs[48] = s0; xs[49] = s1; xs[50] = s2;
            xs[51] = r;
            xs[52] = __int_as_float(ed);
            // radial embedding -> fp16 hi emb tile
            float embv[NRB];
            #pragma unroll
            for (int i = 0; i < NRB; i++) {
                float v = (5.0f / 17.0f) * (float)(i + 1);
                float d = (r - v) * 3.4f;
                float d2 = d * d;
                float y = 0.0f;
                if (d2 < 1.0f) y = 4.56544f * __expf(2.0f - __fdividef(2.0f, 1.0f - d2));
                embv[i] = y;
            }
            #pragma unroll
            for (int i2 = 0; i2 < 8; i2++) {
                __half2 ph = __floats2half2_rn(embv[2 * i2], embv[2 * i2 + 1]);
                *reinterpret_cast<uint32_t*>(smem + OFF_EH + tid * 32 + i2 * 4) =
                    *reinterpret_cast<uint32_t*>(&ph);
            }
        }
        __syncthreads();

        // ============ Phase 2: h-MLP via HMMA -> A fragments directly in registers ============
        uint32_t Ahi[2][4][4];
        {
            uint32_t eh[2][4];
            #pragma unroll
            for (int mf = 0; mf < 2; mf++) {
                int rb = 32 * mi + 16 * mf;
                int o0 = (rb + g) * 32 + 4 * c;
                int o1 = (rb + g + 8) * 32 + 4 * c;
                eh[mf][0] = *reinterpret_cast<const uint32_t*>(smem + OFF_EH + o0);
                eh[mf][1] = *reinterpret_cast<const uint32_t*>(smem + OFF_EH + o1);
                eh[mf][2] = *reinterpret_cast<const uint32_t*>(smem + OFF_EH + o0 + 16);
                eh[mf][3] = *reinterpret_cast<const uint32_t*>(smem + OFF_EH + o1 + 16);
            }
            #pragma unroll
            for (int j = 0; j < 4; j++) {         // j = big-GEMM k-chunk
                float hz[2][2][4];
                #pragma unroll
                for (int mf = 0; mf < 2; mf++)
                    #pragma unroll
                    for (int t = 0; t < 2; t++)
                        #pragma unroll
                        for (int q = 0; q < 4; q++) hz[mf][t][q] = 0.f;
                #pragma unroll
                for (int t = 0; t < 2; t++) {     // n-tile nt = 2j + t (d cols)
                    int n = (2 * j + t) * 8 + g;
                    uint32_t bh[2], bl[2];
                    bh[0] = *reinterpret_cast<const uint32_t*>(smem + OFF_W1H + n * 32 + 4 * c);
                    bh[1] = *reinterpret_cast<const uint32_t*>(smem + OFF_W1H + n * 32 + 16 + 4 * c);
                    bl[0] = *reinterpret_cast<const uint32_t*>(smem + OFF_W1L + n * 32 + 4 * c);
                    bl[1] = *reinterpret_cast<const uint32_t*>(smem + OFF_W1L + n * 32 + 16 + 4 * c);
                    #pragma unroll
                    for (int mf = 0; mf < 2; mf++) {
                        mma_f16(hz[mf][t], eh[mf], bh);
                        mma_f16(hz[mf][t], eh[mf], bl);
                    }
                }
                #pragma unroll
                for (int mf = 0; mf < 2; mf++)
                    #pragma unroll
                    for (int t = 0; t < 2; t++) {
                        float s0 = silu_scaled(hz[mf][t][0]);
                        float s1 = silu_scaled(hz[mf][t][1]);
                        float s2 = silu_scaled(hz[mf][t][2]);
                        float s3 = silu_scaled(hz[mf][t][3]);
                        __half2 p01 = __floats2half2_rn(s0, s1);
                        __half2 p23 = __floats2half2_rn(s2, s3);
                        Ahi[mf][j][2 * t + 0] = *reinterpret_cast<uint32_t*>(&p01);
                        Ahi[mf][j][2 * t + 1] = *reinterpret_cast<uint32_t*>(&p23);
                    }
            }
        }

        // per-edge TP partials: 4 edges (le0, +8, +16, +24)
        float po0p[4][4], cfp[4][2], tpp[4][2][3];
        #pragma unroll
        for (int j = 0; j < 4; j++) {
            #pragma unroll
            for (int s = 0; s < 4; s++) po0p[j][s] = 0.f;
            cfp[j][0] = 0.f; cfp[j][1] = 0.f;
            #pragma unroll
            for (int b = 0; b < 2; b++)
                #pragma unroll
                for (int k = 0; k < 3; k++) tpp[j][b][k] = 0.f;
        }

        // ============ Phase 4: type-specialized GEMM+consume loops ============
        float acc[2][2][4];

        // -- w00: cc in [0,8), u = 2cc + ni --
        for (int cc = 0; cc < 8; cc++) {
            GEMM_CHUNK(cc);
            int u = 2 * cc + ni;
            float xv[4];
            #pragma unroll
            for (int j = 0; j < 4; j++) xv[j] = x_s[(le0 + 8 * j) * XP + u];
            #pragma unroll
            for (int mf = 0; mf < 2; mf++)
                #pragma unroll
                for (int nt = 0; nt < 2; nt++)
                    #pragma unroll
                    for (int q = 0; q < 4; q++) {
                        int j = 2 * mf + (q >> 1);
                        po0p[j][2 * nt + (q & 1)] =
                            fmaf(acc[mf][nt][q], xv[j], po0p[j][2 * nt + (q & 1)]);
                    }
        }
        // -- w01: cc in [8,12), u = 4(cc-8) + 2ni + nt --
        for (int cc = 8; cc < 12; cc++) {
            GEMM_CHUNK(cc);
            int ub = 4 * (cc - 8) + 2 * ni;
            float xv[4][2];
            #pragma unroll
            for (int j = 0; j < 4; j++) {
                xv[j][0] = x_s[(le0 + 8 * j) * XP + ub];
                xv[j][1] = x_s[(le0 + 8 * j) * XP + ub + 1];
            }
            #pragma unroll
            for (int mf = 0; mf < 2; mf++)
                #pragma unroll
                for (int nt = 0; nt < 2; nt++)
                    #pragma unroll
                    for (int q = 0; q < 4; q++) {
                        int j = 2 * mf + (q >> 1);
                        cfp[j][q & 1] = fmaf(acc[mf][nt][q], xv[j][nt], cfp[j][q & 1]);
                    }
        }
        // -- w10: cc in [12,14), u = 4(cc-12) + 2ni + nt --
        for (int cc = 12; cc < 14; cc++) {
            GEMM_CHUNK(cc);
            int ub = 4 * (cc - 12) + 2 * ni;
            float xv[4][2][3];
            #pragma unroll
            for (int j = 0; j < 4; j++)
                #pragma unroll
                for (int nt = 0; nt < 2; nt++)
                    #pragma unroll
                    for (int k = 0; k < 3; k++)
                        xv[j][nt][k] = x_s[(le0 + 8 * j) * XP + 16 + 3 * (ub + nt) + k];
            #pragma unroll
            for (int mf = 0; mf < 2; mf++)
                #pragma unroll
                for (int nt = 0; nt < 2; nt++)
                    #pragma unroll
                    for (int q = 0; q < 4; q++) {
                        int j = 2 * mf + (q >> 1);
                        #pragma unroll
                        for (int k = 0; k < 3; k++)
                            tpp[j][q & 1][k] =
                                fmaf(acc[mf][nt][q], xv[j][nt][k], tpp[j][q & 1][k]);
                    }
        }
        // -- w11: cc in [14,18), u = 2(cc-14) + ni --
        for (int cc = 14; cc < 18; cc++) {
            GEMM_CHUNK(cc);
            int u = 2 * (cc - 14) + ni;
            float dv[4];
            #pragma unroll
            for (int j = 0; j < 4; j++) dv[j] = x_s[(le0 + 8 * j) * XP + 40 + u];
            #pragma unroll
            for (int mf = 0; mf < 2; mf++)
                #pragma unroll
                for (int nt = 0; nt < 2; nt++)
                    #pragma unroll
                    for (int q = 0; q < 4; q++) {
                        int j = 2 * mf + (q >> 1);
                        po0p[j][2 * nt + (q & 1)] =
                            fmaf(acc[mf][nt][q], dv[j], po0p[j][2 * nt + (q & 1)]);
                    }
        }

        // ============ Phase 5: ni-merge through dead x region, then single scatter ============
        __syncthreads();                 // all consume reads of x/dot region complete
        if (ni == 1) {
            #pragma unroll
            for (int j = 0; j < 4; j++) {
                float* mb = x_s + (le0 + 8 * j) * XP + 12 * c;   // [0,48) — dead region
                mb[0] = po0p[j][0]; mb[1] = po0p[j][1];
                mb[2] = po0p[j][2]; mb[3] = po0p[j][3];
                mb[4] = cfp[j][0];  mb[5] = cfp[j][1];
                mb[6] = tpp[j][0][0]; mb[7]  = tpp[j][0][1]; mb[8]  = tpp[j][0][2];
                mb[9] = tpp[j][1][0]; mb[10] = tpp[j][1][1]; mb[11] = tpp[j][1][2];
            }
        }
        __syncthreads();
        if (ni == 0) {
            const float SC = 0.05103103630798288f;   // 1/(sqrt(24)*4)
            #pragma unroll
            for (int j = 0; j < 4; j++) {
                int le = le0 + 8 * j;
                if (tile * E_TILE + le < n_edges) {
                    const float* xs = x_s + le * XP;
                    const float* mb = xs + 12 * c;
                    float p0 = po0p[j][0] + mb[0], p1 = po0p[j][1] + mb[1];
                    float p2 = po0p[j][2] + mb[2], p3 = po0p[j][3] + mb[3];
                    float cf0 = cfp[j][0] + mb[4], cf1 = cfp[j][1] + mb[5];
                    float t00 = tpp[j][0][0] + mb[6],  t01 = tpp[j][0][1] + mb[7];
                    float t02 = tpp[j][0][2] + mb[8];
                    float t10 = tpp[j][1][0] + mb[9],  t11 = tpp[j][1][1] + mb[10];
                    float t12 = tpp[j][1][2] + mb[11];
                    float s0 = xs[48], s1 = xs[49], s2 = xs[50];
                    int dst = __float_as_int(xs[52]);
                    float* base = f_out + (size_t)dst * DIM_F;
                    asm volatile("red.global.add.v2.f32 [%0], {%1, %2};"
                                 :: "l"(base + 2 * c), "f"(p0 * SC), "f"(p1 * SC) : "memory");
                    asm volatile("red.global.add.v2.f32 [%0], {%1, %2};"
                                 :: "l"(base + 8 + 2 * c), "f"(p2 * SC), "f"(p3 * SC) : "memory");
                    float o0 = (cf0 * s0 + t00) * SC;
                    float o1 = (cf0 * s1 + t01) * SC;
                    float o2 = (cf0 * s2 + t02) * SC;
                    float o3 = (cf1 * s0 + t10) * SC;
                    float o4 = (cf1 * s1 + t11) * SC;
                    float o5 = (cf1 * s2 + t12) * SC;
                    float* b1 = base + 16 + 6 * c;
                    asm volatile("red.global.add.v2.f32 [%0], {%1, %2};"
                                 :: "l"(b1), "f"(o0), "f"(o1) : "memory");
                    asm volatile("red.global.add.v2.f32 [%0], {%1, %2};"
                                 :: "l"(b1 + 2), "f"(o2), "f"(o3) : "memory");
                    asm volatile("red.global.add.v2.f32 [%0], {%1, %2};"
                                 :: "l"(b1 + 4), "f"(o4), "f"(o5) : "memory");
                }
            }
        }
        __syncthreads();    // protect x_s / emb before next tile overwrites
    }
}

extern "C" void kernel_launch(void* const* d_in, const int* in_sizes, int n_in,
                              void* d_out, int out_size) {
    const float* pos  = (const float*)d_in[0];
    const float* f_in = (const float*)d_in[1];
    const int*   esrc = (const int*)d_in[2];
    const int*   edst = (const int*)d_in[3];
    const float* W1   = (const float*)d_in[4];
    const float* W2   = (const float*)d_in[5];
    float* out = (float*)d_out;
    int n_edges = in_sizes[2];

    cudaFuncSetAttribute(conv_kernel, cudaFuncAttributeMaxDynamicSharedMemorySize, SMEM_TOTAL);

    int n4 = out_size / 4;
    zero_kernel<<<(n4 + 255) / 256, 256>>>((float4*)out, n4);
    conv_kernel<<<GRID, THREADS, SMEM_TOTAL>>>(pos, f_in, esrc, edst, W1, W2, out, n_edges);
}